// round 1
// baseline (speedup 1.0000x reference)
#include <cuda_runtime.h>

// Problem constants
#define NN 4096   // nodes
#define DD 256    // input dim
#define HH 256    // hidden dim
#define SS 128    // sequence length
#define GRID 148
#define TPB 256
#define RPB 28    // ceil(NN / GRID)

// Persistent device state (allowed scratch: __device__ globals)
__device__ float d_hidden[NN * HH];
__device__ float d_cell[NN * HH];
__device__ float d_HW[NN * HH];      // hidden @ Wn, incrementally maintained
__device__ float d_FS[SS * HH];      // precomputed inputs[seq[t]] @ Ws + bs
__device__ float d_GI[SS * HH];      // precomputed inputs[seq[t]] @ Wg[:D] + bg
__device__ float d_S1[SS * HH];      // per-step accumulator: nei_row @ hidden
__device__ float d_S2[SS * HH];      // per-step accumulator: nei_row @ sigmoid(fs+HW)
__device__ float d_curHid[HH];       // current step's new hidden row
__device__ unsigned d_bar[512];      // grid barrier counters (monotonic)

__device__ __forceinline__ void grid_barrier(int idx) {
    __syncthreads();
    if (threadIdx.x == 0) {
        __threadfence();
        atomicAdd(&d_bar[idx], 1u);
        while (*((volatile unsigned*)&d_bar[idx]) < GRID) { }
        __threadfence();
    }
    __syncthreads();
}

// FMA-only sigmoid: no MUFU. abs error ~1e-5.
__device__ __forceinline__ float fast_sigmoid(float x) {
    float ax = fminf(fabsf(x), 20.0f);
    float m  = ax * 1.4426950408889634f;        // |x| * log2(e), in [0, 28.9]
    float r  = m + 12582912.0f;                 // round-to-nearest-int via magic add
    int   k  = __float_as_int(r) - 0x4B400000;  // integer part
    float kf = r - 12582912.0f;
    float u  = kf - m;                          // u = -frac, in [-0.5, 0.5]
    // 2^u, Taylor/minimax deg-5 on [-0.5, 0.5]
    float p = 0.0013333558f;
    p = fmaf(p, u, 0.0096181291f);
    p = fmaf(p, u, 0.0555041087f);
    p = fmaf(p, u, 0.2402265069f);
    p = fmaf(p, u, 0.6931471806f);
    p = fmaf(p, u, 1.0f);
    float scale = __int_as_float(0x3F800000 - (k << 23));  // 2^-k (k <= 29, safe)
    float t = p * scale;                        // t = exp(-|x|), in (0, 1]
    float s = 1.0f + t;                         // in (1, 2]
    // 1/s: bit-trick init + 2 Newton iterations
    float q = __int_as_float(0x7EF311C3 - __float_as_int(s));
    q = q * fmaf(-s, q, 2.0f);
    q = q * fmaf(-s, q, 2.0f);
    return (x >= 0.0f) ? q : (1.0f - q);
}

__global__ void lstm_init_kernel() {
    int stride = gridDim.x * blockDim.x;
    int e0 = blockIdx.x * blockDim.x + threadIdx.x;
    for (int e = e0; e < 512; e += stride) d_bar[e] = 0u;
    for (int e = e0; e < SS * HH; e += stride) { d_S1[e] = 0.0f; d_S2[e] = 0.0f; }
}

__global__ void __launch_bounds__(TPB) lstm_main_kernel(
    const float* __restrict__ inputs,   // [N, D]
    const float* __restrict__ nei,      // [N, N]
    const float* __restrict__ numNei,   // [N]
    const int*   __restrict__ seq,      // [S]
    const float* __restrict__ h0,       // [N, H]
    const float* __restrict__ c0,       // [N, H]
    const float* __restrict__ Wg,       // [D+H, H]
    const float* __restrict__ bg,       // [H]
    const float* __restrict__ Ws,       // [D, H]
    const float* __restrict__ bs,       // [H]
    const float* __restrict__ Wn,       // [H, H]
    float*       __restrict__ out)      // [N, H]
{
    const int tid = threadIdx.x;
    const int b   = blockIdx.x;
    __shared__ float sh[RPB * 256];     // 28KB: h0 row tile (prologue) / nei slice (loop)

    const int r0  = b * RPB;
    const int cnt = (r0 < NN) ? min(RPB, NN - r0) : 0;

    // ---------- Phase 0a: copy initial state ----------
    for (int e = b * TPB + tid; e < NN * HH; e += GRID * TPB) {
        d_hidden[e] = h0[e];
        d_cell[e]   = c0[e];
    }

    // ---------- Phase 0b: HW0 = h0 @ Wn (this block's row slice) ----------
    for (int r = 0; r < cnt; ++r)
        for (int k = tid; k < 256; k += TPB)
            sh[r * 256 + k] = h0[(size_t)(r0 + r) * 256 + k];
    __syncthreads();
    if (cnt > 0) {
        float acc[RPB];
        #pragma unroll
        for (int r = 0; r < RPB; ++r) acc[r] = 0.0f;
        const int h = tid;
        for (int k = 0; k < 256; ++k) {
            float wn = Wn[k * 256 + h];
            #pragma unroll
            for (int r = 0; r < RPB; ++r)
                acc[r] = fmaf(sh[r * 256 + k], wn, acc[r]);
        }
        for (int r = 0; r < cnt; ++r)
            d_HW[(size_t)(r0 + r) * 256 + h] = acc[r];
    }
    __syncthreads();

    // ---------- Phase 0c: FS[t] = inp@Ws + bs, GI[t] = inp@Wg_top + bg (block t) ----------
    if (b < SS) {
        int i = seq[b];
        for (int k = tid; k < 256; k += TPB) sh[k] = inputs[(size_t)i * 256 + k];
        __syncthreads();
        const int h = tid;
        float fs = bs[h], gi = bg[h];
        for (int k = 0; k < 256; ++k) {
            float iv = sh[k];
            fs = fmaf(iv, Ws[k * 256 + h], fs);
            gi = fmaf(iv, Wg[k * 256 + h], gi);
        }
        d_FS[b * 256 + h] = fs;
        d_GI[b * 256 + h] = gi;
    }

    grid_barrier(0);
    int barIdx = 1;

    const int wid  = tid >> 5;
    const int lane = tid & 31;
    const int h2   = b + 148 * wid;          // wid 0 -> h in [0,147], wid 1 -> [148,255]
    const bool serial_lane = (wid < 2) && (h2 < 256);

    // ---------- Main sequential loop ----------
    for (int t = 0; t < SS; ++t) {
        const int i = __ldg(&seq[t]);

        // Phase 1: streaming reductions S1, S2 over this block's row slice
        if (tid < cnt) sh[tid] = __ldg(&nei[(size_t)i * NN + r0 + tid]);
        __syncthreads();
        {
            const int h = tid;
            float fsv = __ldcg(&d_FS[t * 256 + h]);
            float s1 = 0.0f, s2 = 0.0f;
            const float* hp = d_hidden + (size_t)r0 * 256 + h;
            const float* wp = d_HW     + (size_t)r0 * 256 + h;
            #pragma unroll 4
            for (int r = 0; r < cnt; ++r) {
                float w  = sh[r];
                float hv = __ldcg(hp);
                float hw = __ldcg(wp);
                s1 = fmaf(w, hv, s1);
                s2 = fmaf(w, fast_sigmoid(fsv + hw), s2);
                hp += 256; wp += 256;
            }
            if (cnt > 0) {
                atomicAdd(&d_S1[t * 256 + h], s1);
                atomicAdd(&d_S2[t * 256 + h], s2);
            }
        }
        grid_barrier(barIdx++);

        // Phase 2: pre = GI + (S1/n)@Wn + h_i@Wg_bot ; elementwise cell update
        if (serial_lane) {
            float n = __ldg(&numNei[i]);
            float inv_n = 1.0f / n;
            float dotS = 0.0f, dotG = 0.0f;
            #pragma unroll
            for (int kk = 0; kk < 8; ++kk) {
                int k = lane * 8 + kk;
                float s1v = __ldcg(&d_S1[t * 256 + k]);
                float hik = __ldcg(&d_hidden[(size_t)i * 256 + k]);
                dotS = fmaf(s1v, __ldg(&Wn[k * 256 + h2]), dotS);
                dotG = fmaf(hik, __ldg(&Wg[(256 + k) * 256 + h2]), dotG);
            }
            #pragma unroll
            for (int o = 16; o > 0; o >>= 1) {
                dotS += __shfl_down_sync(0xffffffffu, dotS, o);
                dotG += __shfl_down_sync(0xffffffffu, dotG, o);
            }
            if (lane == 0) {
                float pre = __ldcg(&d_GI[t * 256 + h2]) + inv_n * dotS + dotG;
                float inputState  = 1.0f / (1.0f + expf(-pre));
                float helpCell    = tanhf(pre);
                float fsv = __ldcg(&d_FS[t * 256 + h2]);
                float hwi = __ldcg(&d_HW[(size_t)i * 256 + h2]);
                float forgetState = 1.0f / (1.0f + expf(-(fsv + hwi)));
                float c   = __ldcg(&d_cell[(size_t)i * 256 + h2]);
                float s2v = __ldcg(&d_S2[t * 256 + h2]);
                float curCell   = s2v * inv_n * c + forgetState * c + inputState * helpCell;
                float curHidden = tanhf(inputState * curCell);
                d_cell[(size_t)i * 256 + h2] = curCell;
                d_curHid[h2] = curHidden;
            }
        }
        grid_barrier(barIdx++);

        // Phase 3: HW[i] = curHidden @ Wn ; hidden[i] = curHidden
        if (serial_lane) {
            float dot = 0.0f;
            #pragma unroll
            for (int kk = 0; kk < 8; ++kk) {
                int k = lane * 8 + kk;
                dot = fmaf(__ldcg(&d_curHid[k]), __ldg(&Wn[k * 256 + h2]), dot);
            }
            #pragma unroll
            for (int o = 16; o > 0; o >>= 1)
                dot += __shfl_down_sync(0xffffffffu, dot, o);
            if (lane == 0) {
                d_HW[(size_t)i * 256 + h2]     = dot;
                d_hidden[(size_t)i * 256 + h2] = __ldcg(&d_curHid[h2]);
            }
        }
        grid_barrier(barIdx++);
        __syncthreads();  // protect sh before next step rewrites it
    }

    // ---------- Epilogue: out = hidden + h0 ----------
    for (int e = b * TPB + tid; e < NN * HH; e += GRID * TPB)
        out[e] = __ldcg(&d_hidden[e]) + h0[e];
}

extern "C" void kernel_launch(void* const* d_in, const int* in_sizes, int n_in,
                              void* d_out, int out_size) {
    const float* inputs  = (const float*)d_in[0];
    const float* nei     = (const float*)d_in[1];
    const float* numNei  = (const float*)d_in[2];
    const int*   seq     = (const int*)  d_in[3];
    const float* h0      = (const float*)d_in[4];
    const float* c0      = (const float*)d_in[5];
    const float* Wg      = (const float*)d_in[6];
    const float* bg      = (const float*)d_in[7];
    const float* Ws      = (const float*)d_in[8];
    const float* bs      = (const float*)d_in[9];
    const float* Wn      = (const float*)d_in[10];
    float* out = (float*)d_out;

    lstm_init_kernel<<<64, 256>>>();
    lstm_main_kernel<<<GRID, TPB>>>(inputs, nei, numNei, seq, h0, c0,
                                    Wg, bg, Ws, bs, Wn, out);
}

// round 2
// speedup vs baseline: 1.0105x; 1.0105x over previous
#include <cuda_runtime.h>

// Problem constants
#define NN 4096   // nodes
#define DD 256    // input dim
#define HH 256    // hidden dim
#define SS 128    // sequence length
#define GRID 148
#define TPB 256
#define RPB 28    // ceil(NN / GRID)

// Persistent device state (allowed scratch: __device__ globals)
__device__ float d_hidden[NN * HH];
__device__ float d_cell[NN * HH];
__device__ float d_HW[NN * HH];      // hidden @ Wn, incrementally maintained
__device__ float d_FS[SS * HH];      // precomputed inputs[seq[t]] @ Ws + bs
__device__ float d_GI[SS * HH];      // precomputed inputs[seq[t]] @ Wg[:D] + bg
__device__ float d_S1[SS * HH];      // per-step accumulator: nei_row @ hidden
__device__ float d_S2[SS * HH];      // per-step accumulator: nei_row @ sigmoid(fs+HW)
__device__ float d_curHid[HH];       // current step's new hidden row
__device__ unsigned d_bar[512];      // grid barrier counters (monotonic)

__device__ __forceinline__ void grid_barrier(int idx) {
    __syncthreads();
    if (threadIdx.x == 0) {
        __threadfence();
        atomicAdd(&d_bar[idx], 1u);
        while (*((volatile unsigned*)&d_bar[idx]) < GRID) { }
        __threadfence();
    }
    __syncthreads();
}

// FMA-only sigmoid: no MUFU. abs error ~1e-5.
__device__ __forceinline__ float fast_sigmoid(float x) {
    float ax = fminf(fabsf(x), 20.0f);
    float m  = ax * 1.4426950408889634f;        // |x| * log2(e), in [0, 28.9]
    float r  = m + 12582912.0f;                 // round-to-nearest-int via magic add
    int   k  = __float_as_int(r) - 0x4B400000;  // integer part
    float kf = r - 12582912.0f;
    float u  = kf - m;                          // u = -frac, in [-0.5, 0.5]
    // 2^u, Taylor/minimax deg-5 on [-0.5, 0.5]
    float p = 0.0013333558f;
    p = fmaf(p, u, 0.0096181291f);
    p = fmaf(p, u, 0.0555041087f);
    p = fmaf(p, u, 0.2402265069f);
    p = fmaf(p, u, 0.6931471806f);
    p = fmaf(p, u, 1.0f);
    float scale = __int_as_float(0x3F800000 - (k << 23));  // 2^-k (k <= 29, safe)
    float t = p * scale;                        // t = exp(-|x|), in (0, 1]
    float s = 1.0f + t;                         // in (1, 2]
    // 1/s: bit-trick init + 2 Newton iterations
    float q = __int_as_float(0x7EF311C3 - __float_as_int(s));
    q = q * fmaf(-s, q, 2.0f);
    q = q * fmaf(-s, q, 2.0f);
    return (x >= 0.0f) ? q : (1.0f - q);
}

__global__ void lstm_init_kernel() {
    int stride = gridDim.x * blockDim.x;
    int e0 = blockIdx.x * blockDim.x + threadIdx.x;
    for (int e = e0; e < 512; e += stride) d_bar[e] = 0u;
    for (int e = e0; e < SS * HH; e += stride) { d_S1[e] = 0.0f; d_S2[e] = 0.0f; }
}

__global__ void __launch_bounds__(TPB) lstm_main_kernel(
    const float* __restrict__ inputs,   // [N, D]
    const float* __restrict__ nei,      // [N, N]
    const float* __restrict__ numNei,   // [N]
    const int*   __restrict__ seq,      // [S]
    const float* __restrict__ h0,       // [N, H]
    const float* __restrict__ c0,       // [N, H]
    const float* __restrict__ Wg,       // [D+H, H]
    const float* __restrict__ bg,       // [H]
    const float* __restrict__ Ws,       // [D, H]
    const float* __restrict__ bs,       // [H]
    const float* __restrict__ Wn,       // [H, H]
    float*       __restrict__ out)      // [N, H]
{
    const int tid = threadIdx.x;
    const int b   = blockIdx.x;
    __shared__ float sh[RPB * 256];     // 28KB: h0 row tile (prologue) / nei slice (loop)

    const int r0  = b * RPB;
    const int cnt = (r0 < NN) ? min(RPB, NN - r0) : 0;

    // ---------- Phase 0a: copy initial state ----------
    for (int e = b * TPB + tid; e < NN * HH; e += GRID * TPB) {
        d_hidden[e] = h0[e];
        d_cell[e]   = c0[e];
    }

    // ---------- Phase 0b: HW0 = h0 @ Wn (this block's row slice) ----------
    for (int r = 0; r < cnt; ++r)
        for (int k = tid; k < 256; k += TPB)
            sh[r * 256 + k] = h0[(size_t)(r0 + r) * 256 + k];
    __syncthreads();
    if (cnt > 0) {
        float acc[RPB];
        #pragma unroll
        for (int r = 0; r < RPB; ++r) acc[r] = 0.0f;
        const int h = tid;
        for (int k = 0; k < 256; ++k) {
            float wn = Wn[k * 256 + h];
            #pragma unroll
            for (int r = 0; r < RPB; ++r)
                acc[r] = fmaf(sh[r * 256 + k], wn, acc[r]);
        }
        for (int r = 0; r < cnt; ++r)
            d_HW[(size_t)(r0 + r) * 256 + h] = acc[r];
    }
    __syncthreads();

    // ---------- Phase 0c: FS[t] = inp@Ws + bs, GI[t] = inp@Wg_top + bg (block t) ----------
    if (b < SS) {
        int i = seq[b];
        for (int k = tid; k < 256; k += TPB) sh[k] = inputs[(size_t)i * 256 + k];
        __syncthreads();
        const int h = tid;
        float fs = bs[h], gi = bg[h];
        for (int k = 0; k < 256; ++k) {
            float iv = sh[k];
            fs = fmaf(iv, Ws[k * 256 + h], fs);
            gi = fmaf(iv, Wg[k * 256 + h], gi);
        }
        d_FS[b * 256 + h] = fs;
        d_GI[b * 256 + h] = gi;
    }

    grid_barrier(0);
    int barIdx = 1;

    const int wid  = tid >> 5;
    const int lane = tid & 31;
    const int h2   = b + 148 * wid;          // wid 0 -> h in [0,147], wid 1 -> [148,255]
    const bool serial_lane = (wid < 2) && (h2 < 256);

    // ---------- Main sequential loop ----------
    for (int t = 0; t < SS; ++t) {
        const int i = __ldg(&seq[t]);

        // Phase 1: streaming reductions S1, S2 over this block's row slice
        if (tid < cnt) sh[tid] = __ldg(&nei[(size_t)i * NN + r0 + tid]);
        __syncthreads();
        {
            const int h = tid;
            float fsv = __ldcg(&d_FS[t * 256 + h]);
            float s1 = 0.0f, s2 = 0.0f;
            const float* hp = d_hidden + (size_t)r0 * 256 + h;
            const float* wp = d_HW     + (size_t)r0 * 256 + h;
            #pragma unroll 4
            for (int r = 0; r < cnt; ++r) {
                float w  = sh[r];
                float hv = __ldcg(hp);
                float hw = __ldcg(wp);
                s1 = fmaf(w, hv, s1);
                s2 = fmaf(w, fast_sigmoid(fsv + hw), s2);
                hp += 256; wp += 256;
            }
            if (cnt > 0) {
                atomicAdd(&d_S1[t * 256 + h], s1);
                atomicAdd(&d_S2[t * 256 + h], s2);
            }
        }
        grid_barrier(barIdx++);

        // Phase 2: pre = GI + (S1/n)@Wn + h_i@Wg_bot ; elementwise cell update
        if (serial_lane) {
            float n = __ldg(&numNei[i]);
            float inv_n = 1.0f / n;
            float dotS = 0.0f, dotG = 0.0f;
            #pragma unroll
            for (int kk = 0; kk < 8; ++kk) {
                int k = lane * 8 + kk;
                float s1v = __ldcg(&d_S1[t * 256 + k]);
                float hik = __ldcg(&d_hidden[(size_t)i * 256 + k]);
                dotS = fmaf(s1v, __ldg(&Wn[k * 256 + h2]), dotS);
                dotG = fmaf(hik, __ldg(&Wg[(256 + k) * 256 + h2]), dotG);
            }
            #pragma unroll
            for (int o = 16; o > 0; o >>= 1) {
                dotS += __shfl_down_sync(0xffffffffu, dotS, o);
                dotG += __shfl_down_sync(0xffffffffu, dotG, o);
            }
            if (lane == 0) {
                float pre = __ldcg(&d_GI[t * 256 + h2]) + inv_n * dotS + dotG;
                float inputState  = 1.0f / (1.0f + expf(-pre));
                float helpCell    = tanhf(pre);
                float fsv = __ldcg(&d_FS[t * 256 + h2]);
                float hwi = __ldcg(&d_HW[(size_t)i * 256 + h2]);
                float forgetState = 1.0f / (1.0f + expf(-(fsv + hwi)));
                float c   = __ldcg(&d_cell[(size_t)i * 256 + h2]);
                float s2v = __ldcg(&d_S2[t * 256 + h2]);
                float curCell   = s2v * inv_n * c + forgetState * c + inputState * helpCell;
                float curHidden = tanhf(inputState * curCell);
                d_cell[(size_t)i * 256 + h2] = curCell;
                d_curHid[h2] = curHidden;
            }
        }
        grid_barrier(barIdx++);

        // Phase 3: HW[i] = curHidden @ Wn ; hidden[i] = curHidden
        if (serial_lane) {
            float dot = 0.0f;
            #pragma unroll
            for (int kk = 0; kk < 8; ++kk) {
                int k = lane * 8 + kk;
                dot = fmaf(__ldcg(&d_curHid[k]), __ldg(&Wn[k * 256 + h2]), dot);
            }
            #pragma unroll
            for (int o = 16; o > 0; o >>= 1)
                dot += __shfl_down_sync(0xffffffffu, dot, o);
            if (lane == 0) {
                d_HW[(size_t)i * 256 + h2]     = dot;
                d_hidden[(size_t)i * 256 + h2] = __ldcg(&d_curHid[h2]);
            }
        }
        grid_barrier(barIdx++);
        __syncthreads();  // protect sh before next step rewrites it
    }

    // ---------- Epilogue: out = hidden + h0 ----------
    for (int e = b * TPB + tid; e < NN * HH; e += GRID * TPB)
        out[e] = __ldcg(&d_hidden[e]) + h0[e];
}

extern "C" void kernel_launch(void* const* d_in, const int* in_sizes, int n_in,
                              void* d_out, int out_size) {
    const float* inputs  = (const float*)d_in[0];
    const float* nei     = (const float*)d_in[1];
    const float* numNei  = (const float*)d_in[2];
    const int*   seq     = (const int*)  d_in[3];
    const float* h0      = (const float*)d_in[4];
    const float* c0      = (const float*)d_in[5];
    const float* Wg      = (const float*)d_in[6];
    const float* bg      = (const float*)d_in[7];
    const float* Ws      = (const float*)d_in[8];
    const float* bs      = (const float*)d_in[9];
    const float* Wn      = (const float*)d_in[10];
    float* out = (float*)d_out;

    lstm_init_kernel<<<64, 256>>>();
    lstm_main_kernel<<<GRID, TPB>>>(inputs, nei, numNei, seq, h0, c0,
                                    Wg, bg, Ws, bs, Wn, out);
}

// round 3
// speedup vs baseline: 2.1325x; 2.1103x over previous
#include <cuda_runtime.h>

// Problem constants
#define NN 4096   // nodes
#define DD 256    // input dim
#define HH 256    // hidden dim
#define SS 128    // sequence length
#define GRID 148
#define TPB 512
#define RPB 28    // rows per block (ceil 4096/148)
#define HROWS 14  // rows per thread-half

// Persistent device scratch
__device__ float d_hidden[NN * HH];
__device__ float d_cell[NN * HH];
__device__ float d_HW[NN * HH];      // hidden @ Wn, incrementally maintained
__device__ float d_WnT[HH * HH];     // Wn transposed: WnT[h][k] = Wn[k][h]
__device__ float d_WgT[HH * HH];     // bottom half of Wg transposed: WgT[h][k] = Wg[256+k][h]
__device__ float d_FS[SS * HH];      // inputs[seq[t]] @ Ws + bs
__device__ float d_GI[SS * HH];      // inputs[seq[t]] @ Wg[:256] + bg
__device__ float d_S1[SS * HH];      // nei_row @ hidden accumulator
__device__ float d_S2[SS * HH];      // nei_row @ sigmoid(fs + HW) accumulator
__device__ float d_curHid[HH];       // latest step's new hidden row
__device__ unsigned d_bar[512];      // monotonic grid-barrier counters

// Fast grid barrier: release-RED arrival + acquire-load spin (CG pattern, no MEMBAR.GPU)
__device__ __forceinline__ void grid_barrier(int idx) {
    __syncthreads();
    if (threadIdx.x == 0) {
        unsigned* p = &d_bar[idx];
        asm volatile("red.release.gpu.global.add.u32 [%0], 1;" :: "l"(p) : "memory");
        unsigned v;
        do {
            asm volatile("ld.acquire.gpu.global.u32 %0, [%1];" : "=r"(v) : "l"(p) : "memory");
        } while (v < GRID);
    }
    __syncthreads();
}

// MUFU sigmoid: EX2 + RCP, rel err ~1e-7
__device__ __forceinline__ float sigf(float x) {
    return __fdividef(1.0f, 1.0f + __expf(-x));
}

__global__ void lstm_init_kernel() {
    int stride = gridDim.x * blockDim.x;
    int e0 = blockIdx.x * blockDim.x + threadIdx.x;
    for (int e = e0; e < 512; e += stride) d_bar[e] = 0u;
    for (int e = e0; e < SS * HH; e += stride) { d_S1[e] = 0.0f; d_S2[e] = 0.0f; }
}

__global__ void __launch_bounds__(TPB) lstm_main_kernel(
    const float* __restrict__ inputs,   // [N, D]
    const float* __restrict__ nei,      // [N, N]
    const float* __restrict__ numNei,   // [N]
    const int*   __restrict__ seq,      // [S]
    const float* __restrict__ h0,       // [N, H]
    const float* __restrict__ c0,       // [N, H]
    const float* __restrict__ Wg,       // [D+H, H]
    const float* __restrict__ bg,       // [H]
    const float* __restrict__ Ws,       // [D, H]
    const float* __restrict__ bs,       // [H]
    const float* __restrict__ Wn,       // [H, H]
    float*       __restrict__ out)      // [N, H]
{
    const int tid = threadIdx.x;
    const int b   = blockIdx.x;
    __shared__ float sh[RPB * 256];     // 28KB, multi-purpose
    float* shw  = sh;                    // [28]  nei weights for this block's rows
    float* shs1 = sh + 32;               // [256] half-1 partial S1
    float* shs2 = sh + 288;              // [256] half-1 partial S2

    const int r0  = b * RPB;
    const int cnt = (r0 < NN) ? min(RPB, NN - r0) : 0;

    // ---------- Prologue 0a: copy state + build transposed weights ----------
    for (int e = b * TPB + tid; e < NN * HH; e += GRID * TPB) {
        d_hidden[e] = h0[e];
        d_cell[e]   = c0[e];
    }
    for (int e = b * TPB + tid; e < HH * HH; e += GRID * TPB) {
        int k = e >> 8, h = e & 255;
        d_WnT[h * 256 + k] = Wn[e];
        d_WgT[h * 256 + k] = Wg[(256 + k) * 256 + h];
    }

    // ---------- Prologue 0b: HW0 = h0 @ Wn (this block's row slice) ----------
    for (int e = tid; e < cnt * 256; e += TPB) sh[e] = h0[(size_t)r0 * 256 + e];
    __syncthreads();
    {
        const int h    = tid & 255;
        const int half = tid >> 8;
        const int base = half * HROWS;
        float acc[HROWS];
        #pragma unroll
        for (int r = 0; r < HROWS; ++r) acc[r] = 0.0f;
        for (int k = 0; k < 256; ++k) {
            float wn = __ldg(&Wn[k * 256 + h]);
            #pragma unroll
            for (int r = 0; r < HROWS; ++r)
                acc[r] = fmaf(sh[(base + r) * 256 + k], wn, acc[r]);
        }
        #pragma unroll
        for (int r = 0; r < HROWS; ++r)
            if (base + r < cnt)
                d_HW[(size_t)(r0 + base + r) * 256 + h] = acc[r];
    }
    __syncthreads();

    // ---------- Prologue 0c: FS[t] / GI[t] precompute (block t) ----------
    if (b < SS) {
        int ii = __ldg(&seq[b]);
        for (int k = tid; k < 256; k += TPB) sh[k] = inputs[(size_t)ii * 256 + k];
        __syncthreads();
        if (tid < 256) {
            const int h = tid;
            float fs = bs[h], gi = bg[h];
            for (int k = 0; k < 256; ++k) {
                float iv = sh[k];
                fs = fmaf(iv, __ldg(&Ws[k * 256 + h]), fs);
                gi = fmaf(iv, __ldg(&Wg[k * 256 + h]), gi);
            }
            d_FS[b * 256 + h] = fs;
            d_GI[b * 256 + h] = gi;
        }
    }

    grid_barrier(0);
    int barIdx = 1;

    const int lane  = tid & 31;
    const int wid   = tid >> 5;
    const int h2    = b + 148 * wid;            // owner h: wid0 -> [0,147], wid1 -> [148,255]
    const bool owner = (wid < 2) && (h2 < 256);
    const int hh    = tid & 255;
    const int half  = tid >> 8;
    const int base  = half * HROWS;
    const int cnth  = max(0, min(cnt - base, HROWS));

    // ---------- Main sequential loop: 2 grid barriers per step ----------
    for (int t = 0; t < SS; ++t) {
        const int i    = __ldg(&seq[t]);
        const int prev = (t > 0) ? __ldg(&seq[t - 1]) : -1;
        const size_t tH = (size_t)t * 256;

        // Phase A(a): owners flush step t-1's row update (HW[prev], hidden[prev])
        // and inject row prev's contribution into S1/S2 of step t.
        if (owner && prev >= 0) {
            const float4* ch4 = (const float4*)d_curHid;
            const float4* wn4 = (const float4*)(d_WnT + h2 * 256);
            float dot = 0.0f;
            #pragma unroll
            for (int q = 0; q < 2; ++q) {
                float4 a = __ldcg(&ch4[lane + 32 * q]);
                float4 w = __ldg(&wn4[lane + 32 * q]);
                dot += a.x * w.x + a.y * w.y + a.z * w.z + a.w * w.w;
            }
            #pragma unroll
            for (int o = 16; o; o >>= 1) dot += __shfl_down_sync(0xffffffffu, dot, o);
            if (lane == 0) {
                float ch = __ldcg(&d_curHid[h2]);
                d_HW[(size_t)prev * 256 + h2]     = dot;
                d_hidden[(size_t)prev * 256 + h2] = ch;
                float w   = __ldg(&nei[(size_t)i * NN + prev]);
                float fsv = __ldg(&d_FS[tH + h2]);
                atomicAdd(&d_S1[tH + h2], w * ch);
                atomicAdd(&d_S2[tH + h2], w * sigf(fsv + dot));
            }
        }

        // Phase A(b): stage nei weights, stream this block's row slice (skip prev)
        if (tid < cnt) shw[tid] = __ldg(&nei[(size_t)i * NN + r0 + tid]);
        __syncthreads();
        {
            float fsv = __ldg(&d_FS[tH + hh]);
            float s1 = 0.0f, s2 = 0.0f;
            const float* hp = d_hidden + (size_t)(r0 + base) * 256 + hh;
            const float* wp = d_HW     + (size_t)(r0 + base) * 256 + hh;
            #pragma unroll
            for (int rr = 0; rr < HROWS; ++rr) {
                if (rr < cnth && (r0 + base + rr) != prev) {
                    float w = shw[base + rr];
                    s1 = fmaf(w, __ldcg(hp + rr * 256), s1);
                    s2 = fmaf(w, sigf(fsv + __ldcg(wp + rr * 256)), s2);
                }
            }
            if (half == 1) { shs1[hh] = s1; shs2[hh] = s2; }
            __syncthreads();
            if (half == 0 && cnt > 0) {
                atomicAdd(&d_S1[tH + hh], s1 + shs1[hh]);
                atomicAdd(&d_S2[tH + hh], s2 + shs2[hh]);
            }
        }
        grid_barrier(barIdx++);

        // Phase B: distributed per-h serial update -> cell[i], curHid
        if (owner) {
            const float4* s14 = (const float4*)(d_S1 + tH);
            const float4* hi4 = (const float4*)(d_hidden + (size_t)i * 256);
            const float4* wn4 = (const float4*)(d_WnT + h2 * 256);
            const float4* wg4 = (const float4*)(d_WgT + h2 * 256);
            float dotS = 0.0f, dotG = 0.0f;
            #pragma unroll
            for (int q = 0; q < 2; ++q) {
                float4 a  = __ldcg(&s14[lane + 32 * q]);
                float4 wA = __ldg(&wn4[lane + 32 * q]);
                float4 hl = __ldcg(&hi4[lane + 32 * q]);
                float4 wB = __ldg(&wg4[lane + 32 * q]);
                dotS += a.x * wA.x + a.y * wA.y + a.z * wA.z + a.w * wA.w;
                dotG += hl.x * wB.x + hl.y * wB.y + hl.z * wB.z + hl.w * wB.w;
            }
            #pragma unroll
            for (int o = 16; o; o >>= 1) {
                dotS += __shfl_down_sync(0xffffffffu, dotS, o);
                dotG += __shfl_down_sync(0xffffffffu, dotG, o);
            }
            if (lane == 0) {
                float inv_n = 1.0f / __ldg(&numNei[i]);
                float pre   = __ldg(&d_GI[tH + h2]) + inv_n * dotS + dotG;
                float iS    = sigf(pre);
                float hC    = tanhf(pre);
                float fsv   = __ldg(&d_FS[tH + h2]);
                float fS    = sigf(fsv + __ldcg(&d_HW[(size_t)i * 256 + h2]));
                float c     = __ldcg(&d_cell[(size_t)i * 256 + h2]);
                float s2v   = __ldcg(&d_S2[tH + h2]);
                float cC    = fmaf(s2v * inv_n, c, fmaf(fS, c, iS * hC));
                d_cell[(size_t)i * 256 + h2] = cC;
                d_curHid[h2] = tanhf(iS * cC);
            }
        }
        grid_barrier(barIdx++);
    }

    // ---------- Epilogue: out = hidden + h0 (row i_last still pending in curHid) ----------
    const int ilast = __ldg(&seq[SS - 1]);
    for (int e = b * TPB + tid; e < NN * HH; e += GRID * TPB) {
        int row = e >> 8;
        float hv = (row == ilast) ? __ldcg(&d_curHid[e & 255]) : __ldcg(&d_hidden[e]);
        out[e] = hv + h0[e];
    }
}

extern "C" void kernel_launch(void* const* d_in, const int* in_sizes, int n_in,
                              void* d_out, int out_size) {
    const float* inputs  = (const float*)d_in[0];
    const float* nei     = (const float*)d_in[1];
    const float* numNei  = (const float*)d_in[2];
    const int*   seq     = (const int*)  d_in[3];
    const float* h0      = (const float*)d_in[4];
    const float* c0      = (const float*)d_in[5];
    const float* Wg      = (const float*)d_in[6];
    const float* bg      = (const float*)d_in[7];
    const float* Ws      = (const float*)d_in[8];
    const float* bs      = (const float*)d_in[9];
    const float* Wn      = (const float*)d_in[10];
    float* out = (float*)d_out;

    lstm_init_kernel<<<64, 256>>>();
    lstm_main_kernel<<<GRID, TPB>>>(inputs, nei, numNei, seq, h0, c0,
                                    Wg, bg, Ws, bs, Wn, out);
}